// round 4
// baseline (speedup 1.0000x reference)
#include <cuda_runtime.h>
#include <cstddef>

#define BATCH 16
#define SEQN 2048
#define DIM 128
#define TQ 64
#define TK 64
#define NTHREADS 256
#define NTILES (SEQN / TK)

// Shared layout (floats):
//  sQ4  : [64][32] float4           (Q tile, row-major by float4)
//  sKT4 : [32][65] float4           (K tile, d4-major: sKT4[d4*65 + j] = K[j][4d4..4d4+3]; pad 65 -> conflict-free STS.128/LDS.128)
//  sV4  : [64][32] float4           (V tile, row-major)
//  sS   : [64][68] float            (scores / probs; pad 68)
//  sM, sL, sAlpha : [64]

__device__ __forceinline__ float neg_inf() { return __int_as_float(0xff800000); }

__global__ __launch_bounds__(NTHREADS, 1)
void attn_flash_fp32(const float* __restrict__ q,
                     const float* __restrict__ k,
                     const float* __restrict__ v,
                     float* __restrict__ o) {
    extern __shared__ float smem[];
    float4* sQ4  = reinterpret_cast<float4*>(smem);         // 2048 f4
    float4* sKT4 = sQ4 + 64 * 32;                           // 2080 f4
    float4* sV4  = sKT4 + 32 * 65;                          // 2048 f4
    float*  sS   = reinterpret_cast<float*>(sV4 + 64 * 32); // 64*68 f
    float*  sM     = sS + 64 * 68;
    float*  sL     = sM + 64;
    float*  sAlpha = sL + 64;

    const int tid = threadIdx.x;
    const int b = blockIdx.y;
    const int qbase = blockIdx.x * TQ;

    const int ty = tid >> 4;   // 0..15 : owns rows ty*4 .. ty*4+3
    const int tx = tid & 15;   // 0..15 : S-phase keys {tx,tx+16,tx+32,tx+48}; PV-phase dims {4tx.., 64+4tx..}

    // ---- stage Q tile ----
    {
        const float4* qg = reinterpret_cast<const float4*>(q + ((size_t)b * SEQN + qbase) * DIM);
        #pragma unroll
        for (int idx = tid; idx < TQ * (DIM / 4); idx += NTHREADS)
            sQ4[idx] = qg[idx];
    }
    if (tid < TQ) { sM[tid] = neg_inf(); sL[tid] = 0.0f; }

    float accO[4][8];
    #pragma unroll
    for (int i = 0; i < 4; ++i)
        #pragma unroll
        for (int c = 0; c < 8; ++c) accO[i][c] = 0.0f;

    __syncthreads();

    for (int kt = 0; kt < NTILES; ++kt) {
        // ---- stage K (chunk-transposed) and V ----
        const float4* kg = reinterpret_cast<const float4*>(k + ((size_t)b * SEQN + kt * TK) * DIM);
        const float4* vg = reinterpret_cast<const float4*>(v + ((size_t)b * SEQN + kt * TK) * DIM);
        #pragma unroll
        for (int idx = tid; idx < TK * (DIM / 4); idx += NTHREADS) {
            int j  = idx >> 5;   // key row 0..63
            int d4 = idx & 31;   // float4-chunk of head dim
            sKT4[d4 * 65 + j] = kg[idx];
            sV4[idx] = vg[idx];
        }
        __syncthreads();

        // ---- S = Q K^T  (4x4 micro-tile, float4 component accumulators) ----
        float4 acc4[4][4];
        #pragma unroll
        for (int i = 0; i < 4; ++i)
            #pragma unroll
            for (int c = 0; c < 4; ++c)
                acc4[i][c] = make_float4(0.f, 0.f, 0.f, 0.f);

        #pragma unroll 2
        for (int d4 = 0; d4 < 32; ++d4) {
            float4 kq[4];
            #pragma unroll
            for (int c = 0; c < 4; ++c)
                kq[c] = sKT4[d4 * 65 + tx + 16 * c];
            #pragma unroll
            for (int i = 0; i < 4; ++i) {
                float4 qv = sQ4[(ty * 4 + i) * 32 + d4];
                #pragma unroll
                for (int c = 0; c < 4; ++c) {
                    acc4[i][c].x += qv.x * kq[c].x;
                    acc4[i][c].y += qv.y * kq[c].y;
                    acc4[i][c].z += qv.z * kq[c].z;
                    acc4[i][c].w += qv.w * kq[c].w;
                }
            }
        }
        #pragma unroll
        for (int i = 0; i < 4; ++i) {
            int row = ty * 4 + i;
            #pragma unroll
            for (int c = 0; c < 4; ++c) {
                float4 a = acc4[i][c];
                sS[row * 68 + tx + 16 * c] = (a.x + a.y) + (a.z + a.w);
            }
        }
        __syncthreads();

        // ---- online softmax (4 threads per row) ----
        {
            const int row  = tid >> 2;
            const int part = tid & 3;
            float* rowp = sS + row * 68 + part * 16;
            float4 e[4];
            #pragma unroll
            for (int p = 0; p < 4; ++p) e[p] = reinterpret_cast<float4*>(rowp)[p];

            float mloc = neg_inf();
            #pragma unroll
            for (int p = 0; p < 4; ++p) {
                mloc = fmaxf(mloc, fmaxf(fmaxf(e[p].x, e[p].y), fmaxf(e[p].z, e[p].w)));
            }
            mloc = fmaxf(mloc, __shfl_xor_sync(0xffffffffu, mloc, 1));
            mloc = fmaxf(mloc, __shfl_xor_sync(0xffffffffu, mloc, 2));

            float mold = sM[row];
            float mnew = fmaxf(mold, mloc);

            float sum = 0.0f;
            #pragma unroll
            for (int p = 0; p < 4; ++p) {
                e[p].x = __expf(e[p].x - mnew);
                e[p].y = __expf(e[p].y - mnew);
                e[p].z = __expf(e[p].z - mnew);
                e[p].w = __expf(e[p].w - mnew);
                sum += (e[p].x + e[p].y) + (e[p].z + e[p].w);
                reinterpret_cast<float4*>(rowp)[p] = e[p];
            }
            sum += __shfl_xor_sync(0xffffffffu, sum, 1);
            sum += __shfl_xor_sync(0xffffffffu, sum, 2);

            if (part == 0) {
                float alpha = __expf(mold - mnew);   // first tile: exp(-inf)=0
                sAlpha[row] = alpha;
                sM[row] = mnew;
                sL[row] = sL[row] * alpha + sum;
            }
        }
        __syncthreads();

        // ---- O = O*alpha + P V ----
        #pragma unroll
        for (int i = 0; i < 4; ++i) {
            float a = sAlpha[ty * 4 + i];
            #pragma unroll
            for (int c = 0; c < 8; ++c) accO[i][c] *= a;
        }
        #pragma unroll 2
        for (int j = 0; j < TK; ++j) {
            float4 v0 = sV4[j * 32 + tx];
            float4 v1 = sV4[j * 32 + 16 + tx];
            #pragma unroll
            for (int i = 0; i < 4; ++i) {
                float p = sS[(ty * 4 + i) * 68 + j];
                accO[i][0] += p * v0.x;
                accO[i][1] += p * v0.y;
                accO[i][2] += p * v0.z;
                accO[i][3] += p * v0.w;
                accO[i][4] += p * v1.x;
                accO[i][5] += p * v1.y;
                accO[i][6] += p * v1.z;
                accO[i][7] += p * v1.w;
            }
        }
        __syncthreads();   // protect sKT4/sV4 before next staging
    }

    // ---- epilogue: normalize + store ----
    #pragma unroll
    for (int i = 0; i < 4; ++i) {
        int row = ty * 4 + i;
        float inv = 1.0f / sL[row];
        float4 o0 = make_float4(accO[i][0] * inv, accO[i][1] * inv,
                                accO[i][2] * inv, accO[i][3] * inv);
        float4 o1 = make_float4(accO[i][4] * inv, accO[i][5] * inv,
                                accO[i][6] * inv, accO[i][7] * inv);
        float4* og = reinterpret_cast<float4*>(o + ((size_t)b * SEQN + qbase + row) * DIM);
        og[tx] = o0;
        og[16 + tx] = o1;
    }
}

extern "C" void kernel_launch(void* const* d_in, const int* in_sizes, int n_in,
                              void* d_out, int out_size) {
    (void)in_sizes; (void)n_in; (void)out_size;
    const float* q = (const float*)d_in[0];
    const float* k = (const float*)d_in[1];
    const float* v = (const float*)d_in[2];
    float* o = (float*)d_out;

    // sQ4 2048 f4 + sKT4 2080 f4 + sV4 2048 f4 = 6176*16 B; sS 64*68*4 B; stats 3*64*4 B
    const int smem_bytes = 6176 * 16 + 64 * 68 * 4 + 3 * 64 * 4;  // 116992

    // Unconditional (no static guard — deterministic launch path). Not a
    // stream operation, so it is legal under graph capture.
    cudaFuncSetAttribute(attn_flash_fp32,
                         cudaFuncAttributeMaxDynamicSharedMemorySize, smem_bytes);

    dim3 grid(SEQN / TQ, BATCH);
    attn_flash_fp32<<<grid, NTHREADS, smem_bytes>>>(q, k, v, o);
}

// round 7
// speedup vs baseline: 5.4590x; 5.4590x over previous
#include <cuda_runtime.h>
#include <cuda_fp16.h>
#include <cstdint>
#include <cstddef>

#define BATCH 16
#define SEQN 2048
#define DIM 128
#define TQ 128
#define TK 64
#define NKT (SEQN / TK)   // 32
#define NTHREADS 256

// ---------------- scratch (fragment-ordered fp16 copies) ----------------
// QF: per (b, qtile16) 8192B: [hl][kt 8][lane 32][a0..a3 16B]
// KF: per (b, ktile64) 32768B: [hl][kt 8][nt 8][lane 32][b0,b1 8B]
// VF: per (b, ktile64) 16384B: [kc 4][nt 16][lane 32][b0,b1 8B]
__device__ __align__(16) unsigned char g_QF[(size_t)16 * 128 * 8192];
__device__ __align__(16) unsigned char g_KF[(size_t)16 * 32 * 32768];
__device__ __align__(16) unsigned char g_VF[(size_t)16 * 32 * 16384];

__device__ __forceinline__ uint32_t packh(float x, float y) {
    __half2 h = __floats2half2_rn(x, y);
    return *reinterpret_cast<uint32_t*>(&h);
}
__device__ __forceinline__ void split(float x, float& hi, float& lo) {
    __half h = __float2half_rn(x);
    hi = __half2float(h);
    lo = x - hi;
}

// mma.sync m16n8k16 row.col f32.f16.f16.f32 (sm_80+ PTX; arch-neutral)
__device__ __forceinline__ void mma16816(float* c, const uint32_t* a, const uint32_t* b) {
    asm volatile(
        "mma.sync.aligned.m16n8k16.row.col.f32.f16.f16.f32 "
        "{%0,%1,%2,%3}, {%4,%5,%6,%7}, {%8,%9}, {%0,%1,%2,%3};"
        : "+f"(c[0]), "+f"(c[1]), "+f"(c[2]), "+f"(c[3])
        : "r"(a[0]), "r"(a[1]), "r"(a[2]), "r"(a[3]), "r"(b[0]), "r"(b[1]));
}

__device__ __forceinline__ void cp16(uint32_t saddr, const void* gaddr) {
    asm volatile("cp.async.cg.shared.global [%0], [%1], 16;" :: "r"(saddr), "l"(gaddr));
}
__device__ __forceinline__ uint32_t smem_u32(const void* p) {
    uint32_t a;
    asm("{ .reg .u64 t; cvta.to.shared.u64 t, %1; cvt.u32.u64 %0, t; }" : "=r"(a) : "l"(p));
    return a;
}

// ---------------- prep kernels ----------------
// A-frag layout (m16n8k16): groupID g = lane>>2, tig t = lane&3
//  a0:(row g,   k t*2,t*2+1) a1:(row g+8, k t*2..) a2:(row g, k t*2+8..) a3:(row g+8, k t*2+8..)
// B-frag: b0:(k t*2,t*2+1, col g)  b1:(k t*2+8,t*2+9, col g)
// C-frag: c0:(g, t*2) c1:(g, t*2+1) c2:(g+8, t*2) c3:(g+8, t*2+1)

__global__ void prep_q(const float* __restrict__ q) {
    int tid = blockIdx.x * blockDim.x + threadIdx.x;   // 2^19 threads
    int lane = tid & 31, kt = (tid >> 5) & 7, qt = (tid >> 8) & 127, b = tid >> 15;
    int g = lane >> 2, t = lane & 3;
    int row = qt * 16 + g, d0 = kt * 16 + t * 2;
    const float* qb = q + ((size_t)b * SEQN) * DIM;
    float2 x00 = *(const float2*)(qb + (size_t)row * DIM + d0);
    float2 x10 = *(const float2*)(qb + (size_t)(row + 8) * DIM + d0);
    float2 x01 = *(const float2*)(qb + (size_t)row * DIM + d0 + 8);
    float2 x11 = *(const float2*)(qb + (size_t)(row + 8) * DIM + d0 + 8);
    float h, l;
    uint4 hi, lo;
    float l00x, l00y, l10x, l10y, l01x, l01y, l11x, l11y;
    float h00x, h00y, h10x, h10y, h01x, h01y, h11x, h11y;
    split(x00.x, h00x, l00x); split(x00.y, h00y, l00y);
    split(x10.x, h10x, l10x); split(x10.y, h10y, l10y);
    split(x01.x, h01x, l01x); split(x01.y, h01y, l01y);
    split(x11.x, h11x, l11x); split(x11.y, h11y, l11y);
    (void)h; (void)l;
    hi.x = packh(h00x, h00y); hi.y = packh(h10x, h10y);
    hi.z = packh(h01x, h01y); hi.w = packh(h11x, h11y);
    lo.x = packh(l00x, l00y); lo.y = packh(l10x, l10y);
    lo.z = packh(l01x, l01y); lo.w = packh(l11x, l11y);
    unsigned char* base = g_QF + ((size_t)(b * 128 + qt)) * 8192;
    *(uint4*)(base + (0 * 8 + kt) * 512 + lane * 16) = hi;
    *(uint4*)(base + (1 * 8 + kt) * 512 + lane * 16) = lo;
}

__global__ void prep_k(const float* __restrict__ k) {
    int tid = blockIdx.x * blockDim.x + threadIdx.x;   // 2^20 threads
    int lane = tid & 31, nt = (tid >> 5) & 7, kt = (tid >> 8) & 7,
        tile = (tid >> 11) & 31, b = tid >> 16;
    int g = lane >> 2, t = lane & 3;
    int key = tile * 64 + nt * 8 + g, d0 = kt * 16 + t * 2;
    const float* kb = k + ((size_t)b * SEQN) * DIM;
    float2 f0 = *(const float2*)(kb + (size_t)key * DIM + d0);
    float2 f1 = *(const float2*)(kb + (size_t)key * DIM + d0 + 8);
    float h0x, l0x, h0y, l0y, h1x, l1x, h1y, l1y;
    split(f0.x, h0x, l0x); split(f0.y, h0y, l0y);
    split(f1.x, h1x, l1x); split(f1.y, h1y, l1y);
    uint2 hi = {packh(h0x, h0y), packh(h1x, h1y)};
    uint2 lo = {packh(l0x, l0y), packh(l1x, l1y)};
    unsigned char* base = g_KF + ((size_t)(b * 32 + tile)) * 32768;
    *(uint2*)(base + ((0 * 8 + kt) * 8 + nt) * 256 + lane * 8) = hi;
    *(uint2*)(base + ((1 * 8 + kt) * 8 + nt) * 256 + lane * 8) = lo;
}

__global__ void prep_v(const float* __restrict__ v) {
    int tid = blockIdx.x * blockDim.x + threadIdx.x;   // 2^20 threads
    int lane = tid & 31, nt = (tid >> 5) & 15, kc = (tid >> 9) & 3,
        tile = (tid >> 11) & 31, b = tid >> 16;
    int g = lane >> 2, t = lane & 3;
    int k0 = tile * 64 + kc * 16 + t * 2, dim = nt * 8 + g;
    const float* vb = v + ((size_t)b * SEQN) * DIM;
    float v00 = vb[(size_t)k0 * DIM + dim];
    float v01 = vb[(size_t)(k0 + 1) * DIM + dim];
    float v08 = vb[(size_t)(k0 + 8) * DIM + dim];
    float v09 = vb[(size_t)(k0 + 9) * DIM + dim];
    uint2 bf = {packh(v00, v01), packh(v08, v09)};
    unsigned char* base = g_VF + ((size_t)(b * 32 + tile)) * 16384;
    *(uint2*)(base + (kc * 16 + nt) * 256 + lane * 8) = bf;
}

// ---------------- main attention kernel ----------------
// smem: [0,64K) Q frags [warp][hl][kt][lane]16B ; [64K,64K+2*48K) double-buffered K/V tile
#define SQ_OFF 0
#define SKV_OFF 65536
#define BUF_STRIDE 49152
#define SMEM_BYTES (65536 + 2 * 49152)   // 163840

__global__ __launch_bounds__(NTHREADS, 1)
void attn_mma_fp16(float* __restrict__ o) {
    extern __shared__ unsigned char sm[];
    const int tid = threadIdx.x, warp = tid >> 5, lane = tid & 31;
    const int g = lane >> 2, t = lane & 3;
    const int b = blockIdx.y, bx = blockIdx.x;
    const uint32_t sbase = smem_u32(sm);

    // stage Q (64KB contiguous; qtiles bx*8..bx*8+7 match warp order)
    {
        const unsigned char* gq = g_QF + ((size_t)(b * 128 + bx * 8)) * 8192;
        #pragma unroll
        for (int i = 0; i < 16; ++i)
            cp16(sbase + SQ_OFF + (i * 256 + tid) * 16, gq + (size_t)(i * 256 + tid) * 16);
    }
    // stage tile 0
    {
        const unsigned char* gk = g_KF + ((size_t)(b * 32 + 0)) * 32768;
        const unsigned char* gv = g_VF + ((size_t)(b * 32 + 0)) * 16384;
        uint32_t sk = sbase + SKV_OFF;
        #pragma unroll
        for (int i = 0; i < 8; ++i)
            cp16(sk + (i * 256 + tid) * 16, gk + (size_t)(i * 256 + tid) * 16);
        #pragma unroll
        for (int i = 0; i < 4; ++i)
            cp16(sk + 32768 + (i * 256 + tid) * 16, gv + (size_t)(i * 256 + tid) * 16);
    }
    asm volatile("cp.async.commit_group;");
    asm volatile("cp.async.wait_group 0;");
    __syncthreads();

    float O[16][4];
    #pragma unroll
    for (int n = 0; n < 16; ++n)
        #pragma unroll
        for (int j = 0; j < 4; ++j) O[n][j] = 0.0f;
    float M0 = -1e30f, M1 = -1e30f, L0 = 0.0f, L1 = 0.0f;

    for (int kt0 = 0; kt0 < NKT; ++kt0) {
        // prefetch next tile
        if (kt0 + 1 < NKT) {
            int nb = (kt0 + 1) & 1;
            const unsigned char* gk = g_KF + ((size_t)(b * 32 + kt0 + 1)) * 32768;
            const unsigned char* gv = g_VF + ((size_t)(b * 32 + kt0 + 1)) * 16384;
            uint32_t sk = sbase + SKV_OFF + nb * BUF_STRIDE;
            #pragma unroll
            for (int i = 0; i < 8; ++i)
                cp16(sk + (i * 256 + tid) * 16, gk + (size_t)(i * 256 + tid) * 16);
            #pragma unroll
            for (int i = 0; i < 4; ++i)
                cp16(sk + 32768 + (i * 256 + tid) * 16, gv + (size_t)(i * 256 + tid) * 16);
            asm volatile("cp.async.commit_group;");
            asm volatile("cp.async.wait_group 1;");
        } else {
            asm volatile("cp.async.wait_group 0;");
        }
        __syncthreads();

        const unsigned char* skf = sm + SKV_OFF + (kt0 & 1) * BUF_STRIDE;
        const unsigned char* svf = skf + 32768;

        // ---- S = Qh*Kh + Qh*Kl + Ql*Kh ----
        float c[8][4];
        #pragma unroll
        for (int n = 0; n < 8; ++n)
            #pragma unroll
            for (int j = 0; j < 4; ++j) c[n][j] = 0.0f;

        #pragma unroll
        for (int kt = 0; kt < 8; ++kt) {
            uint4 ah = *(const uint4*)(sm + SQ_OFF + ((warp * 2 + 0) * 8 + kt) * 512 + lane * 16);
            uint4 al = *(const uint4*)(sm + SQ_OFF + ((warp * 2 + 1) * 8 + kt) * 512 + lane * 16);
            #pragma unroll
            for (int nt = 0; nt < 8; ++nt) {
                uint2 bh = *(const uint2*)(skf + ((0 * 8 + kt) * 8 + nt) * 256 + lane * 8);
                uint2 bl = *(const uint2*)(skf + ((1 * 8 + kt) * 8 + nt) * 256 + lane * 8);
                mma16816(c[nt], (const uint32_t*)&ah, (const uint32_t*)&bh);
                mma16816(c[nt], (const uint32_t*)&ah, (const uint32_t*)&bl);
                mma16816(c[nt], (const uint32_t*)&al, (const uint32_t*)&bh);
            }
        }

        // ---- online softmax ----
        float mx0 = -1e30f, mx1 = -1e30f;
        #pragma unroll
        for (int n = 0; n < 8; ++n) {
            mx0 = fmaxf(mx0, fmaxf(c[n][0], c[n][1]));
            mx1 = fmaxf(mx1, fmaxf(c[n][2], c[n][3]));
        }
        mx0 = fmaxf(mx0, __shfl_xor_sync(0xffffffffu, mx0, 1));
        mx0 = fmaxf(mx0, __shfl_xor_sync(0xffffffffu, mx0, 2));
        mx1 = fmaxf(mx1, __shfl_xor_sync(0xffffffffu, mx1, 1));
        mx1 = fmaxf(mx1, __shfl_xor_sync(0xffffffffu, mx1, 2));
        float mn0 = fmaxf(M0, mx0), mn1 = fmaxf(M1, mx1);
        float al0 = __expf(M0 - mn0), al1 = __expf(M1 - mn1);
        M0 = mn0; M1 = mn1;

        float s0 = 0.0f, s1 = 0.0f;
        uint32_t pha[8][2], pla[8][2];
        #pragma unroll
        for (int n = 0; n < 8; ++n) {
            float p0 = __expf(c[n][0] - mn0), p1 = __expf(c[n][1] - mn0);
            float p2 = __expf(c[n][2] - mn1), p3 = __expf(c[n][3] - mn1);
            s0 += p0 + p1; s1 += p2 + p3;
            float h0, l0, h1, l1, h2, l2, h3, l3;
            split(p0, h0, l0); split(p1, h1, l1);
            split(p2, h2, l2); split(p3, h3, l3);
            pha[n][0] = packh(h0, h1); pha[n][1] = packh(h2, h3);
            pla[n][0] = packh(l0, l1); pla[n][1] = packh(l2, l3);
        }
        s0 += __shfl_xor_sync(0xffffffffu, s0, 1);
        s0 += __shfl_xor_sync(0xffffffffu, s0, 2);
        s1 += __shfl_xor_sync(0xffffffffu, s1, 1);
        s1 += __shfl_xor_sync(0xffffffffu, s1, 2);
        L0 = L0 * al0 + s0;
        L1 = L1 * al1 + s1;

        #pragma unroll
        for (int n = 0; n < 16; ++n) {
            O[n][0] *= al0; O[n][1] *= al0;
            O[n][2] *= al1; O[n][3] *= al1;
        }

        // ---- O += (Ph + Pl) * V ----
        #pragma unroll
        for (int kc = 0; kc < 4; ++kc) {
            uint32_t ah[4] = {pha[2 * kc][0], pha[2 * kc][1], pha[2 * kc + 1][0], pha[2 * kc + 1][1]};
            uint32_t alr[4] = {pla[2 * kc][0], pla[2 * kc][1], pla[2 * kc + 1][0], pla[2 * kc + 1][1]};
            #pragma unroll
            for (int nt = 0; nt < 16; ++nt) {
                uint2 bv = *(const uint2*)(svf + (kc * 16 + nt) * 256 + lane * 8);
                mma16816(O[nt], ah, (const uint32_t*)&bv);
                mma16816(O[nt], alr, (const uint32_t*)&bv);
            }
        }
        __syncthreads();   // all warps done with this buffer before it is restaged
    }

    // ---- epilogue ----
    float inv0 = 1.0f / L0, inv1 = 1.0f / L1;
    int row0 = bx * TQ + warp * 16 + g;
    float* ob = o + ((size_t)b * SEQN + row0) * DIM;
    #pragma unroll
    for (int nt = 0; nt < 16; ++nt) {
        int d0 = nt * 8 + t * 2;
        float2 r0 = {O[nt][0] * inv0, O[nt][1] * inv0};
        float2 r1 = {O[nt][2] * inv1, O[nt][3] * inv1};
        *(float2*)(ob + d0) = r0;
        *(float2*)(ob + (size_t)8 * DIM + d0) = r1;
    }
}

extern "C" void kernel_launch(void* const* d_in, const int* in_sizes, int n_in,
                              void* d_out, int out_size) {
    (void)in_sizes; (void)n_in; (void)out_size;
    const float* q = (const float*)d_in[0];
    const float* k = (const float*)d_in[1];
    const float* v = (const float*)d_in[2];
    float* o = (float*)d_out;

    prep_q<<<2048, 256>>>(q);   // 2^19 threads
    prep_k<<<4096, 256>>>(k);   // 2^20
    prep_v<<<4096, 256>>>(v);   // 2^20

    cudaFuncSetAttribute(attn_mma_fp16,
                         cudaFuncAttributeMaxDynamicSharedMemorySize, SMEM_BYTES);
    dim3 grid(SEQN / TQ, BATCH);   // 16 x 16
    attn_mma_fp16<<<grid, NTHREADS, SMEM_BYTES>>>(o);
}

// round 8
// speedup vs baseline: 6.1182x; 1.1208x over previous
#include <cuda_runtime.h>
#include <cuda_fp16.h>
#include <cstdint>
#include <cstddef>

#define BATCH 16
#define SEQN 2048
#define DIM 128
#define TQ 128
#define TK 64
#define NKT (SEQN / TK)   // 32
#define NTHREADS 256

// ---------------- scratch (fragment-ordered fp16 copies) ----------------
// QF: per (b, qtile16) 8192B: [hl][kt 8][lane 32][a0..a3 16B]
// KF: per (b, ktile64) 32768B: [hl][kt 8][nt 8][lane 32][b0,b1 8B]
// VF: per (b, ktile64) 16384B: [kc 4][nt 16][lane 32][b0,b1 8B]
__device__ __align__(16) unsigned char g_QF[(size_t)16 * 128 * 8192];
__device__ __align__(16) unsigned char g_KF[(size_t)16 * 32 * 32768];
__device__ __align__(16) unsigned char g_VF[(size_t)16 * 32 * 16384];

__device__ __forceinline__ uint32_t packh(float x, float y) {
    __half2 h = __floats2half2_rn(x, y);
    return *reinterpret_cast<uint32_t*>(&h);
}
__device__ __forceinline__ void split(float x, float& hi, float& lo) {
    __half h = __float2half_rn(x);
    hi = __half2float(h);
    lo = x - hi;
}

// mma.sync m16n8k16 row.col f32.f16.f16.f32 (sm_80+ PTX; arch-neutral)
__device__ __forceinline__ void mma16816(float* c, const uint32_t* a, const uint32_t* b) {
    asm volatile(
        "mma.sync.aligned.m16n8k16.row.col.f32.f16.f16.f32 "
        "{%0,%1,%2,%3}, {%4,%5,%6,%7}, {%8,%9}, {%0,%1,%2,%3};"
        : "+f"(c[0]), "+f"(c[1]), "+f"(c[2]), "+f"(c[3])
        : "r"(a[0]), "r"(a[1]), "r"(a[2]), "r"(a[3]), "r"(b[0]), "r"(b[1]));
}

__device__ __forceinline__ void cp16(uint32_t saddr, const void* gaddr) {
    asm volatile("cp.async.cg.shared.global [%0], [%1], 16;" :: "r"(saddr), "l"(gaddr));
}
__device__ __forceinline__ uint32_t smem_u32(const void* p) {
    uint32_t a;
    asm("{ .reg .u64 t; cvta.to.shared.u64 t, %1; cvt.u32.u64 %0, t; }" : "=r"(a) : "l"(p));
    return a;
}

// ---------------- prep kernels (unchanged from R7, proven) ----------------

__global__ void prep_q(const float* __restrict__ q) {
    int tid = blockIdx.x * blockDim.x + threadIdx.x;   // 2^19 threads
    int lane = tid & 31, kt = (tid >> 5) & 7, qt = (tid >> 8) & 127, b = tid >> 15;
    int g = lane >> 2, t = lane & 3;
    int row = qt * 16 + g, d0 = kt * 16 + t * 2;
    const float* qb = q + ((size_t)b * SEQN) * DIM;
    float2 x00 = *(const float2*)(qb + (size_t)row * DIM + d0);
    float2 x10 = *(const float2*)(qb + (size_t)(row + 8) * DIM + d0);
    float2 x01 = *(const float2*)(qb + (size_t)row * DIM + d0 + 8);
    float2 x11 = *(const float2*)(qb + (size_t)(row + 8) * DIM + d0 + 8);
    uint4 hi, lo;
    float l00x, l00y, l10x, l10y, l01x, l01y, l11x, l11y;
    float h00x, h00y, h10x, h10y, h01x, h01y, h11x, h11y;
    split(x00.x, h00x, l00x); split(x00.y, h00y, l00y);
    split(x10.x, h10x, l10x); split(x10.y, h10y, l10y);
    split(x01.x, h01x, l01x); split(x01.y, h01y, l01y);
    split(x11.x, h11x, l11x); split(x11.y, h11y, l11y);
    hi.x = packh(h00x, h00y); hi.y = packh(h10x, h10y);
    hi.z = packh(h01x, h01y); hi.w = packh(h11x, h11y);
    lo.x = packh(l00x, l00y); lo.y = packh(l10x, l10y);
    lo.z = packh(l01x, l01y); lo.w = packh(l11x, l11y);
    unsigned char* base = g_QF + ((size_t)(b * 128 + qt)) * 8192;
    *(uint4*)(base + (0 * 8 + kt) * 512 + lane * 16) = hi;
    *(uint4*)(base + (1 * 8 + kt) * 512 + lane * 16) = lo;
}

__global__ void prep_k(const float* __restrict__ k) {
    int tid = blockIdx.x * blockDim.x + threadIdx.x;   // 2^20 threads
    int lane = tid & 31, nt = (tid >> 5) & 7, kt = (tid >> 8) & 7,
        tile = (tid >> 11) & 31, b = tid >> 16;
    int g = lane >> 2, t = lane & 3;
    int key = tile * 64 + nt * 8 + g, d0 = kt * 16 + t * 2;
    const float* kb = k + ((size_t)b * SEQN) * DIM;
    float2 f0 = *(const float2*)(kb + (size_t)key * DIM + d0);
    float2 f1 = *(const float2*)(kb + (size_t)key * DIM + d0 + 8);
    float h0x, l0x, h0y, l0y, h1x, l1x, h1y, l1y;
    split(f0.x, h0x, l0x); split(f0.y, h0y, l0y);
    split(f1.x, h1x, l1x); split(f1.y, h1y, l1y);
    uint2 hi = {packh(h0x, h0y), packh(h1x, h1y)};
    uint2 lo = {packh(l0x, l0y), packh(l1x, l1y)};
    unsigned char* base = g_KF + ((size_t)(b * 32 + tile)) * 32768;
    *(uint2*)(base + ((0 * 8 + kt) * 8 + nt) * 256 + lane * 8) = hi;
    *(uint2*)(base + ((1 * 8 + kt) * 8 + nt) * 256 + lane * 8) = lo;
}

__global__ void prep_v(const float* __restrict__ v) {
    int tid = blockIdx.x * blockDim.x + threadIdx.x;   // 2^20 threads
    int lane = tid & 31, nt = (tid >> 5) & 15, kc = (tid >> 9) & 3,
        tile = (tid >> 11) & 31, b = tid >> 16;
    int g = lane >> 2, t = lane & 3;
    int k0 = tile * 64 + kc * 16 + t * 2, dim = nt * 8 + g;
    const float* vb = v + ((size_t)b * SEQN) * DIM;
    float v00 = vb[(size_t)k0 * DIM + dim];
    float v01 = vb[(size_t)(k0 + 1) * DIM + dim];
    float v08 = vb[(size_t)(k0 + 8) * DIM + dim];
    float v09 = vb[(size_t)(k0 + 9) * DIM + dim];
    uint2 bf = {packh(v00, v01), packh(v08, v09)};
    unsigned char* base = g_VF + ((size_t)(b * 32 + tile)) * 16384;
    *(uint2*)(base + (kc * 16 + nt) * 256 + lane * 8) = bf;
}

// ---------------- main attention kernel ----------------
// smem: [0,64K) Q frags ; [64K,128K) K double buf (32K each) ; [128K,176K) V triple buf (16K each)
#define SQ_OFF 0
#define SK_OFF 65536
#define SV_OFF 131072
#define SMEM_BYTES 180224

__global__ __launch_bounds__(NTHREADS, 1)
void attn_mma_fp16(float* __restrict__ o) {
    extern __shared__ unsigned char sm[];
    const int tid = threadIdx.x, warp = tid >> 5, lane = tid & 31;
    const int g = lane >> 2, t = lane & 3;
    const int b = blockIdx.y, bx = blockIdx.x;
    const uint32_t sbase = smem_u32(sm);

    // ---- preamble: stage Q + KV(0) as cp.async group 0 ----
    {
        const unsigned char* gq = g_QF + ((size_t)(b * 128 + bx * 8)) * 8192;
        #pragma unroll
        for (int i = 0; i < 16; ++i)
            cp16(sbase + SQ_OFF + (i * 256 + tid) * 16, gq + (size_t)(i * 256 + tid) * 16);
        const unsigned char* gk = g_KF + ((size_t)(b * 32 + 0)) * 32768;
        const unsigned char* gv = g_VF + ((size_t)(b * 32 + 0)) * 16384;
        #pragma unroll
        for (int i = 0; i < 8; ++i)
            cp16(sbase + SK_OFF + (i * 256 + tid) * 16, gk + (size_t)(i * 256 + tid) * 16);
        #pragma unroll
        for (int i = 0; i < 4; ++i)
            cp16(sbase + SV_OFF + (i * 256 + tid) * 16, gv + (size_t)(i * 256 + tid) * 16);
        asm volatile("cp.async.commit_group;");
    }

    float O[16][4];
    #pragma unroll
    for (int n = 0; n < 16; ++n)
        #pragma unroll
        for (int j = 0; j < 4; ++j) O[n][j] = 0.0f;
    float M0 = -1e30f, M1 = -1e30f, L0 = 0.0f, L1 = 0.0f;
    uint32_t Pf[8][2];   // P(t-1) hi fragments

    int vprev = 2, vcur = 0, vnext = 1;   // rotating V buffer indices (t-1, t, t+1)

    for (int kt0 = 0; kt0 < NKT; ++kt0) {
        // KV(kt0) (group kt0) complete in this thread, then publish to all warps.
        asm volatile("cp.async.wait_group 0;");
        __syncthreads();

        // prefetch KV(kt0+1) — targets kbuf[(kt0+1)&1] (last read: QK(kt0-1), pre-barrier)
        // and vbuf[vnext] (last read: PV(kt0-2), pre-barrier). No races.
        if (kt0 + 1 < NKT) {
            const unsigned char* gk = g_KF + ((size_t)(b * 32 + kt0 + 1)) * 32768;
            const unsigned char* gv = g_VF + ((size_t)(b * 32 + kt0 + 1)) * 16384;
            uint32_t sk = sbase + SK_OFF + (((kt0 + 1) & 1) ? 32768u : 0u);
            uint32_t sv = sbase + SV_OFF + (uint32_t)vnext * 16384u;
            #pragma unroll
            for (int i = 0; i < 8; ++i)
                cp16(sk + (i * 256 + tid) * 16, gk + (size_t)(i * 256 + tid) * 16);
            #pragma unroll
            for (int i = 0; i < 4; ++i)
                cp16(sv + (i * 256 + tid) * 16, gv + (size_t)(i * 256 + tid) * 16);
            asm volatile("cp.async.commit_group;");
        }

        const unsigned char* skf = sm + SK_OFF + ((kt0 & 1) ? 32768 : 0);

        // ---- QK(t): S = Qh*Kh + Qh*Kl + Ql*Kh ----
        float c[8][4];
        #pragma unroll
        for (int n = 0; n < 8; ++n)
            #pragma unroll
            for (int j = 0; j < 4; ++j) c[n][j] = 0.0f;

        #pragma unroll
        for (int kt = 0; kt < 8; ++kt) {
            uint4 ah = *(const uint4*)(sm + SQ_OFF + ((warp * 2 + 0) * 8 + kt) * 512 + lane * 16);
            uint4 al = *(const uint4*)(sm + SQ_OFF + ((warp * 2 + 1) * 8 + kt) * 512 + lane * 16);
            #pragma unroll
            for (int nt = 0; nt < 8; ++nt) {
                uint2 bh = *(const uint2*)(skf + ((0 * 8 + kt) * 8 + nt) * 256 + lane * 8);
                uint2 bl = *(const uint2*)(skf + ((1 * 8 + kt) * 8 + nt) * 256 + lane * 8);
                mma16816(c[nt], (const uint32_t*)&ah, (const uint32_t*)&bh);
                mma16816(c[nt], (const uint32_t*)&ah, (const uint32_t*)&bl);
                mma16816(c[nt], (const uint32_t*)&al, (const uint32_t*)&bh);
            }
        }

        // ---- PV(t-1): O += P(t-1) * V(t-1)  (hi-only; overlaps with softmax below) ----
        if (kt0 > 0) {
            const unsigned char* svf = sm + SV_OFF + vprev * 16384;
            #pragma unroll
            for (int kc = 0; kc < 4; ++kc) {
                uint32_t ap[4] = {Pf[2 * kc][0], Pf[2 * kc][1],
                                  Pf[2 * kc + 1][0], Pf[2 * kc + 1][1]};
                #pragma unroll
                for (int nt = 0; nt < 16; ++nt) {
                    uint2 bv = *(const uint2*)(svf + (kc * 16 + nt) * 256 + lane * 8);
                    mma16816(O[nt], ap, (const uint32_t*)&bv);
                }
            }
        }

        // ---- softmax(t): update M/L, build P(t) frags, rescale O ----
        float mx0 = -1e30f, mx1 = -1e30f;
        #pragma unroll
        for (int n = 0; n < 8; ++n) {
            mx0 = fmaxf(mx0, fmaxf(c[n][0], c[n][1]));
            mx1 = fmaxf(mx1, fmaxf(c[n][2], c[n][3]));
        }
        mx0 = fmaxf(mx0, __shfl_xor_sync(0xffffffffu, mx0, 1));
        mx0 = fmaxf(mx0, __shfl_xor_sync(0xffffffffu, mx0, 2));
        mx1 = fmaxf(mx1, __shfl_xor_sync(0xffffffffu, mx1, 1));
        mx1 = fmaxf(mx1, __shfl_xor_sync(0xffffffffu, mx1, 2));
        float mn0 = fmaxf(M0, mx0), mn1 = fmaxf(M1, mx1);
        float al0 = __expf(M0 - mn0), al1 = __expf(M1 - mn1);
        M0 = mn0; M1 = mn1;

        float s0 = 0.0f, s1 = 0.0f;
        #pragma unroll
        for (int n = 0; n < 8; ++n) {
            float p0 = __expf(c[n][0] - mn0), p1 = __expf(c[n][1] - mn0);
            float p2 = __expf(c[n][2] - mn1), p3 = __expf(c[n][3] - mn1);
            s0 += p0 + p1; s1 += p2 + p3;
            Pf[n][0] = packh(p0, p1);
            Pf[n][1] = packh(p2, p3);
        }
        s0 += __shfl_xor_sync(0xffffffffu, s0, 1);
        s0 += __shfl_xor_sync(0xffffffffu, s0, 2);
        s1 += __shfl_xor_sync(0xffffffffu, s1, 1);
        s1 += __shfl_xor_sync(0xffffffffu, s1, 2);
        L0 = L0 * al0 + s0;
        L1 = L1 * al1 + s1;

        #pragma unroll
        for (int n = 0; n < 16; ++n) {
            O[n][0] *= al0; O[n][1] *= al0;
            O[n][2] *= al1; O[n][3] *= al1;
        }

        int tmp = vprev; vprev = vcur; vcur = vnext; vnext = tmp;
    }

    // ---- tail: PV(NKT-1) ----
    {
        const unsigned char* svf = sm + SV_OFF + vprev * 16384;
        #pragma unroll
        for (int kc = 0; kc < 4; ++kc) {
            uint32_t ap[4] = {Pf[2 * kc][0], Pf[2 * kc][1],
                              Pf[2 * kc + 1][0], Pf[2 * kc + 1][1]};
            #pragma unroll
            for (int nt = 0; nt < 16; ++nt) {
                uint2 bv = *(const uint2*)(svf + (kc * 16 + nt) * 256 + lane * 8);
                mma16816(O[nt], ap, (const uint32_t*)&bv);
            }
        }
    }

    // ---- epilogue ----
    float inv0 = 1.0f / L0, inv1 = 1.0f / L1;
    int row0 = bx * TQ + warp * 16 + g;
    float* ob = o + ((size_t)b * SEQN + row0) * DIM;
    #pragma unroll
    for (int nt = 0; nt < 16; ++nt) {
        int d0 = nt * 8 + t * 2;
        float2 r0 = {O[nt][0] * inv0, O[nt][1] * inv0};
        float2 r1 = {O[nt][2] * inv1, O[nt][3] * inv1};
        *(float2*)(ob + d0) = r0;
        *(float2*)(ob + (size_t)8 * DIM + d0) = r1;
    }
}

extern "C" void kernel_launch(void* const* d_in, const int* in_sizes, int n_in,
                              void* d_out, int out_size) {
    (void)in_sizes; (void)n_in; (void)out_size;
    const float* q = (const float*)d_in[0];
    const float* k = (const float*)d_in[1];
    const float* v = (const float*)d_in[2];
    float* o = (float*)d_out;

    prep_q<<<2048, 256>>>(q);   // 2^19 threads
    prep_k<<<4096, 256>>>(k);   // 2^20
    prep_v<<<4096, 256>>>(v);   // 2^20

    cudaFuncSetAttribute(attn_mma_fp16,
                         cudaFuncAttributeMaxDynamicSharedMemorySize, SMEM_BYTES);
    dim3 grid(SEQN / TQ, BATCH);   // 16 x 16
    attn_mma_fp16<<<grid, NTHREADS, SMEM_BYTES>>>(o);
}